// round 6
// baseline (speedup 1.0000x reference)
#include <cuda_runtime.h>

// ---------------------------------------------------------------------------
// Overlaps: out[i,j] = IoU(boxes0[i], boxes1[j]) if (label,batch) match else 0.
// Match probability = 1/(80*8) = 1/640 -> output is 99.84% zeros.
//
// SINGLE fused kernel (grid = n0+1 blocks):
//   block 0:      bucket side-1 indices into fixed-stride lists (smem hist,
//                 no scan), __threadfence, set g_flag.
//   blocks 1..n0: zero-fill their 40KB row (STG.128, DRAM-bound ~56us),
//                 spin-wait g_flag (block 0 finishes in ~5us, first-wave fill
//                 takes ~7us -> spin is free), overwrite ~16 matching columns.
// Replay-safe: last finishing block resets g_flag/g_done to initial state.
// ---------------------------------------------------------------------------

#define NUM_CLASSES 80
#define NUM_IMAGES  8
#define NB          (NUM_CLASSES * NUM_IMAGES)   // 640 buckets
#define CAP         128                          // slots per bucket (avg ~15.6)
#define TPB         256

__device__ int g_cnt1[NB];
__device__ int g_list1[NB * CAP];
__device__ volatile int g_flag;   // 0 initially; reset by last block each launch
__device__ unsigned int g_done;   // finished-block counter, reset each launch

__global__ void __launch_bounds__(TPB)
k_fused(const float* __restrict__ b0,
        const float* __restrict__ b1,
        const int* __restrict__ lab0, const int* __restrict__ bat0,
        const int* __restrict__ lab1, const int* __restrict__ bat1,
        float* __restrict__ out, int n0, int n1) {
    int t = threadIdx.x;

    if (blockIdx.x == 0) {
        // ---- producer: bucket side 1 ----
        __shared__ int cnt[NB];
        for (int k = t; k < NB; k += TPB) cnt[k] = 0;
        __syncthreads();

        for (int i = t; i < n1; i += TPB) {
            int k = lab1[i] * NUM_IMAGES + bat1[i];
            int p = atomicAdd(&cnt[k], 1);
            if (p < CAP) g_list1[k * CAP + p] = i;
        }
        __syncthreads();

        for (int k = t; k < NB; k += TPB)
            g_cnt1[k] = cnt[k] < CAP ? cnt[k] : CAP;
        __threadfence();
        __syncthreads();
        if (t == 0) g_flag = 1;          // release lists to consumers
    } else {
        // ---- consumer: one row per block ----
        int i = blockIdx.x - 1;
        long rowbase = (long)i * n1;
        float4* row4 = reinterpret_cast<float4*>(out + rowbase);
        int n4 = n1 >> 2;

        // 1. stream zeros over this row (coalesced 16B stores)
        const float4 z = make_float4(0.f, 0.f, 0.f, 0.f);
        #pragma unroll 4
        for (int c = t; c < n4; c += TPB) row4[c] = z;
        for (int c = (n4 << 2) + t; c < n1; c += TPB) out[rowbase + c] = 0.f;

        // 2. wait for bucket lists (block 0 is wave-1; usually already done)
        __syncthreads();
        if (t == 0) {
            while (g_flag == 0) __nanosleep(64);
        }
        __syncthreads();
        __threadfence();                 // acquire: order list reads after flag

        // 3. overwrite the matching columns with IoU
        int key = lab0[i] * NUM_IMAGES + bat0[i];
        int cnt = g_cnt1[key];
        const int* list = &g_list1[key * CAP];
        float4 A = *reinterpret_cast<const float4*>(b0 + 4 * (long)i);
        float areaA = (A.z - A.x) * (A.w - A.y);

        for (int s = t; s < cnt; s += TPB) {
            int j = list[s];
            float4 B = *reinterpret_cast<const float4*>(b1 + 4 * (long)j);
            float x1 = fmaxf(A.x, B.x);
            float y1 = fmaxf(A.y, B.y);
            float x2 = fminf(A.z, B.z);
            float y2 = fminf(A.w, B.w);
            float inter = fmaxf(x2 - x1, 0.f) * fmaxf(y2 - y1, 0.f);
            float areaB = (B.z - B.x) * (B.w - B.y);
            float un = areaA + areaB - inter;
            float iou = (un > 0.f) ? (inter / un) : 0.f;
            out[rowbase + j] = iou;
        }
    }

    // ---- replay-safe state reset: last block restores initial state ----
    __syncthreads();
    if (t == 0) {
        unsigned int total = (unsigned int)(n0 + 1);
        unsigned int d = atomicAdd(&g_done, 1u) + 1u;
        if (d == total) {
            g_flag = 0;
            g_done = 0u;
            __threadfence();
        }
    }
}

// ---------------------------------------------------------------------------
extern "C" void kernel_launch(void* const* d_in, const int* in_sizes, int n_in,
                              void* d_out, int out_size) {
    const float* b0   = (const float*)d_in[0];
    const int*   lab0 = (const int*)  d_in[1];
    const int*   bat0 = (const int*)  d_in[2];
    const float* b1   = (const float*)d_in[3];
    const int*   lab1 = (const int*)  d_in[4];
    const int*   bat1 = (const int*)  d_in[5];
    float* out = (float*)d_out;

    int n0 = in_sizes[0] / 4;
    int n1 = in_sizes[3] / 4;

    k_fused<<<n0 + 1, TPB>>>(b0, b1, lab0, bat0, lab1, bat1, out, n0, n1);
}